// round 15
// baseline (speedup 1.0000x reference)
#include <cuda_runtime.h>

#define N_NODES 50000
#define N_EDGES 200000
#define IN_C    32
#define HID     32
#define OUT_C   16
#define EDGE_DIM 8
#define LN_EPS  1e-5f

typedef unsigned long long u64;

// scatter accumulator; zero-initialized at module load; node_kernel re-zeroes
// it after consuming, so the invariant holds across graph replays.
__device__ float g_agg[N_NODES * HID];

__device__ __forceinline__ u64 ffma2(u64 a, u64 b, u64 c) {
    u64 d;
    asm("fma.rn.f32x2 %0, %1, %2, %3;" : "=l"(d) : "l"(a), "l"(b), "l"(c));
    return d;
}
__device__ __forceinline__ u64 add2(u64 a, u64 b) {
    u64 d;
    asm("add.rn.f32x2 %0, %1, %2;" : "=l"(d) : "l"(a), "l"(b));
    return d;
}
__device__ __forceinline__ u64 dup2(float s) {
    unsigned u = __float_as_uint(s);
    return ((u64)u << 32) | (u64)u;
}
__device__ __forceinline__ u64 pack2(float lo, float hi) {
    return ((u64)__float_as_uint(hi) << 32) | (u64)__float_as_uint(lo);
}
__device__ __forceinline__ float lo2(u64 v) { return __uint_as_float((unsigned)v); }
__device__ __forceinline__ float hi2(u64 v) { return __uint_as_float((unsigned)(v >> 32)); }

__device__ __forceinline__ unsigned tf32_of(float f) {
    unsigned r;
    asm("cvt.rna.tf32.f32 %0, %1;" : "=r"(r) : "f"(f));
    return r;
}
// paired no-return reduction (8B-aligned)
__device__ __forceinline__ void red2(float* p, float a, float b) {
    asm volatile("red.global.add.v2.f32 [%0], {%1, %2};"
        :: "l"(p), "f"(a), "f"(b) : "memory");
}

// ---------------------------------------------------------------------------
// Edge kernel: tf32 mma.sync MLP + direct-register x rows (no smem staging).
// Lane (g4 = lane>>2, t4 = lane&3) owns edges g4 and g4+8 of the 16-edge
// group; it loads both x[src] rows itself (4 t4-lanes share addresses -> L1
// broadcast), consumed in 8-feature chunks with next-chunk prefetch. No
// per-group __syncwarp, no ssrc/sdst/xs shared state.
// ---------------------------------------------------------------------------
__global__ __launch_bounds__(128) void edge_kernel(
    const float* __restrict__ x,
    const int*   __restrict__ edge_index,
    const float* __restrict__ edge_attr,
    const float* __restrict__ nn_w,
    const float* __restrict__ nn_b)
{
    __shared__ u64 sbp[1024 * 4];   // (b1|b0): idx = col*4 + k   32 KB
    __shared__ u64 sbias[512];      // [i*16 + t4*4 + c] pair      4 KB

    const int tid = threadIdx.x;

    for (int idx = tid; idx < 4096; idx += 128) {
        const int col = idx >> 2, k = idx & 3;
        const unsigned b0 = tf32_of(nn_w[k * 1024 + col]);
        const unsigned b1 = tf32_of(nn_w[(k + 4) * 1024 + col]);
        sbp[idx] = ((u64)b1 << 32) | (u64)b0;
    }
    for (int idx = tid; idx < 512; idx += 128) {
        const int i = idx >> 4, r = idx & 15;
        const int tt4 = r >> 2, c = r & 3;
        const int t = i * 4 + c;
        const int col0 = 8 * t + 2 * tt4;
        sbias[idx] = pack2(nn_b[col0], nn_b[col0 + 1]);
    }
    __syncthreads();

    const int lane = tid & 31;
    const int warp = tid >> 5;
    const int g4 = lane >> 2;
    const int t4 = lane & 3;
    const int nGroups = N_EDGES / 16;   // 12500, exact

    for (int g = blockIdx.x * 4 + warp; g < nGroups; g += gridDim.x * 4) {
        const int e0 = g * 16;

        // indices: direct loads (4 lanes dup -> broadcast)
        const int srcA = edge_index[e0 + g4];
        const int srcB = edge_index[e0 + g4 + 8];
        const int dstA = edge_index[N_EDGES + e0 + g4] * HID;
        const int dstB = edge_index[N_EDGES + e0 + g4 + 8] * HID;

        // A fragments from gmem (small, L1-hot)
        const float* eaP = edge_attr + (size_t)e0 * EDGE_DIM;
        const unsigned a0 = tf32_of(eaP[g4 * 8 + t4]);
        const unsigned a1 = tf32_of(eaP[(g4 + 8) * 8 + t4]);
        const unsigned a2 = tf32_of(eaP[g4 * 8 + t4 + 4]);
        const unsigned a3 = tf32_of(eaP[(g4 + 8) * 8 + t4 + 4]);

        const float4* xA = (const float4*)(x + (size_t)srcA * IN_C);
        const float4* xB = (const float4*)(x + (size_t)srcB * IN_C);
        float4 fA0 = xA[0], fA1 = xA[1];     // chunk 0: feats 0..7
        float4 fB0 = xB[0], fB1 = xB[1];

        float msgA[8], msgB[8];
        #pragma unroll
        for (int m = 0; m < 8; ++m) { msgA[m] = 0.f; msgB[m] = 0.f; }

        #pragma unroll
        for (int hc = 0; hc < 4; ++hc) {
            const float xAf[8] = {fA0.x, fA0.y, fA0.z, fA0.w, fA1.x, fA1.y, fA1.z, fA1.w};
            const float xBf[8] = {fB0.x, fB0.y, fB0.z, fB0.w, fB1.x, fB1.y, fB1.z, fB1.w};
            if (hc < 3) {                    // prefetch next chunk under compute
                fA0 = xA[2 * hc + 2]; fA1 = xA[2 * hc + 3];
                fB0 = xB[2 * hc + 2]; fB1 = xB[2 * hc + 3];
            }
            #pragma unroll
            for (int ii = 0; ii < 8; ++ii) {
                const int i = hc * 8 + ii;
                const float xv0 = xAf[ii];
                const float xv1 = xBf[ii];
                const ulonglong2* bp = (const ulonglong2*)&sbias[i * 16 + t4 * 4];
                const ulonglong2 cb01 = bp[0];
                const ulonglong2 cb23 = bp[1];
                const u64 cbs[4] = {cb01.x, cb01.y, cb23.x, cb23.y};
                #pragma unroll
                for (int c = 0; c < 4; ++c) {
                    const int t = i * 4 + c;
                    const u64 bb = sbp[(8 * t + g4) * 4 + t4];   // LDS.64
                    const unsigned b0 = (unsigned)bb;
                    const unsigned b1 = (unsigned)(bb >> 32);
                    float d0 = lo2(cbs[c]), d1 = hi2(cbs[c]), d2 = d0, d3 = d1;
                    asm("mma.sync.aligned.m16n8k8.row.col.f32.tf32.tf32.f32 "
                        "{%0,%1,%2,%3}, {%4,%5,%6,%7}, {%8,%9}, {%0,%1,%2,%3};"
                        : "+f"(d0), "+f"(d1), "+f"(d2), "+f"(d3)
                        : "r"(a0), "r"(a1), "r"(a2), "r"(a3), "r"(b0), "r"(b1));
                    d0 = fmaxf(d0, 0.f); d1 = fmaxf(d1, 0.f);
                    d2 = fmaxf(d2, 0.f); d3 = fmaxf(d3, 0.f);
                    msgA[2 * c + 0] = fmaf(xv0, d0, msgA[2 * c + 0]);
                    msgA[2 * c + 1] = fmaf(xv0, d1, msgA[2 * c + 1]);
                    msgB[2 * c + 0] = fmaf(xv1, d2, msgB[2 * c + 0]);
                    msgB[2 * c + 1] = fmaf(xv1, d3, msgB[2 * c + 1]);
                }
            }
        }

        #pragma unroll
        for (int c = 0; c < 4; ++c) {
            const int o = 8 * c + 2 * t4;
            red2(&g_agg[dstA + o], msgA[2 * c + 0], msgA[2 * c + 1]);
            red2(&g_agg[dstB + o], msgB[2 * c + 0], msgB[2 * c + 1]);
        }
    }
}

// ---------------------------------------------------------------------------
// Node kernel (unchanged from R14 measured config).
// ---------------------------------------------------------------------------
__global__ __launch_bounds__(256) void node_kernel(
    const float* __restrict__ x,
    const float* __restrict__ root,
    const float* __restrict__ bias,
    const float* __restrict__ norm_w,
    const float* __restrict__ norm_b,
    const float* __restrict__ lin_w,
    const float* __restrict__ lin_b,
    float* __restrict__ out)
{
    __shared__ u64 root2[IN_C * 16];
    __shared__ u64 lw2[HID * 8];
    __shared__ u64 bias2[16], nw2[16], nb2[16];
    __shared__ float lb_s[OUT_C];

    const int tid = threadIdx.x;
    for (int idx = tid; idx < IN_C * 16; idx += 256) {
        const int i = idx >> 4, pr = idx & 15;
        const float2 v = *(const float2*)(root + i * HID + 2 * pr);
        root2[idx] = pack2(v.x, v.y);
    }
    for (int idx = tid; idx < HID * 8; idx += 256) {
        const int k = idx >> 3, op = idx & 7;
        const float2 v = *(const float2*)(lin_w + k * OUT_C + 2 * op);
        lw2[idx] = pack2(v.x, v.y);
    }
    if (tid < 16) {
        const float2 b = *(const float2*)(bias + 2 * tid);
        const float2 w = *(const float2*)(norm_w + 2 * tid);
        const float2 nb = *(const float2*)(norm_b + 2 * tid);
        bias2[tid] = pack2(b.x, b.y);
        nw2[tid]   = pack2(w.x, w.y);
        nb2[tid]   = pack2(nb.x, nb.y);
    }
    if (tid < OUT_C) lb_s[tid] = lin_b[tid];
    __syncthreads();

    const int t = blockIdx.x * 256 + tid;
    const int rawNode = t >> 1;
    const bool valid = rawNode < N_NODES;
    const int node = valid ? rawNode : (N_NODES - 1);
    const int sub  = t & 1;
    const int fb   = sub * 16;
    const int pb   = sub * 8;

    const float4* aggp = (const float4*)(g_agg + (size_t)node * HID + fb);
    u64 h2[8];
    #pragma unroll
    for (int q = 0; q < 4; ++q) {
        const float4 a = aggp[q];
        h2[2 * q + 0] = add2(pack2(a.x, a.y), bias2[pb + 2 * q + 0]);
        h2[2 * q + 1] = add2(pack2(a.z, a.w), bias2[pb + 2 * q + 1]);
    }

    const float4* xp = (const float4*)(x + (size_t)node * IN_C);
    const ulonglong2* r2 = (const ulonglong2*)root2;
    #pragma unroll
    for (int half = 0; half < 2; ++half) {
        float xf[16];
        #pragma unroll
        for (int q = 0; q < 4; ++q) {
            const float4 v = xp[half * 4 + q];
            xf[q * 4 + 0] = v.x; xf[q * 4 + 1] = v.y;
            xf[q * 4 + 2] = v.z; xf[q * 4 + 3] = v.w;
        }
        #pragma unroll
        for (int ii = 0; ii < 16; ++ii) {
            const int i = half * 16 + ii;
            const u64 xi2 = dup2(xf[ii]);
            #pragma unroll
            for (int q = 0; q < 4; ++q) {
                const ulonglong2 rr = r2[i * 8 + 4 * sub + q];
                h2[2 * q + 0] = ffma2(xi2, rr.x, h2[2 * q + 0]);
                h2[2 * q + 1] = ffma2(xi2, rr.y, h2[2 * q + 1]);
            }
        }
    }

    float s = 0.f;
    #pragma unroll
    for (int j = 0; j < 8; ++j) s += lo2(h2[j]) + hi2(h2[j]);
    s += __shfl_xor_sync(0xffffffffu, s, 1);
    const float mu = s * (1.0f / HID);
    const u64 negmu2 = dup2(-mu);

    u64 vacc = 0ull;
    #pragma unroll
    for (int j = 0; j < 8; ++j) {
        h2[j] = add2(h2[j], negmu2);
        vacc = ffma2(h2[j], h2[j], vacc);
    }
    float v = lo2(vacc) + hi2(vacc);
    v += __shfl_xor_sync(0xffffffffu, v, 1);
    const float inv = rsqrtf(v * (1.0f / HID) + LN_EPS);
    const u64 inv2 = dup2(inv);

    float h[16];
    #pragma unroll
    for (int j = 0; j < 8; ++j) {
        u64 t2 = ffma2(h2[j], inv2, 0ull);
        t2 = ffma2(t2, nw2[pb + j], nb2[pb + j]);
        h[2 * j + 0] = fmaxf(lo2(t2), 0.f);
        h[2 * j + 1] = fmaxf(hi2(t2), 0.f);
    }

    u64 res2[8];
    #pragma unroll
    for (int op = 0; op < 8; ++op) res2[op] = 0ull;
    const ulonglong2* l2 = (const ulonglong2*)lw2;
    #pragma unroll
    for (int k = 0; k < 16; ++k) {
        const u64 hv2 = dup2(h[k]);
        #pragma unroll
        for (int q = 0; q < 4; ++q) {
            const ulonglong2 w = l2[(fb + k) * 4 + q];
            res2[2 * q + 0] = ffma2(hv2, w.x, res2[2 * q + 0]);
            res2[2 * q + 1] = ffma2(hv2, w.y, res2[2 * q + 1]);
        }
    }
    float res[OUT_C];
    #pragma unroll
    for (int op = 0; op < 8; ++op) {
        float rl = lo2(res2[op]), rh = hi2(res2[op]);
        rl += __shfl_xor_sync(0xffffffffu, rl, 1);
        rh += __shfl_xor_sync(0xffffffffu, rh, 1);
        res[2 * op + 0] = rl;
        res[2 * op + 1] = rh;
    }

    if (valid) {
        float4* ragg = (float4*)(g_agg + (size_t)node * HID + fb);
        const float4 z4 = make_float4(0.f, 0.f, 0.f, 0.f);
        ragg[0] = z4; ragg[1] = z4; ragg[2] = z4; ragg[3] = z4;
        float* op = out + (size_t)node * OUT_C;
        #pragma unroll
        for (int oo = 0; oo < OUT_C; ++oo)
            if ((oo >> 3) == sub) op[oo] = res[oo] + lb_s[oo];
    }
}

extern "C" void kernel_launch(void* const* d_in, const int* in_sizes, int n_in,
                              void* d_out, int out_size) {
    const float* x          = (const float*)d_in[0];
    const int*   edge_index = (const int*)  d_in[1];
    const float* edge_attr  = (const float*)d_in[2];
    const float* nn_w       = (const float*)d_in[3];
    const float* nn_b       = (const float*)d_in[4];
    const float* root       = (const float*)d_in[5];
    const float* bias       = (const float*)d_in[6];
    const float* norm_w     = (const float*)d_in[7];
    const float* norm_b     = (const float*)d_in[8];
    const float* lin_w      = (const float*)d_in[9];
    const float* lin_b      = (const float*)d_in[10];
    float* out = (float*)d_out;

    edge_kernel<<<625, 128>>>(x, edge_index, edge_attr, nn_w, nn_b);
    node_kernel<<<(N_NODES * 2 + 255) / 256, 256>>>(x, root, bias, norm_w, norm_b,
                                                    lin_w, lin_b, out);
}